// round 6
// baseline (speedup 1.0000x reference)
#include <cuda_runtime.h>
#include <cstdint>
#include <cstddef>

#define NN   50000
#define NE   800000
#define DD   128
#define KTOT 256
#define BM   128
#define BK   32
#define NTHR 256
#define SCAN_BLKS 196   // ceil(50000/256)

// ---------------- scratch (device globals; no allocation allowed) -----------
__device__ __align__(16) float g_agg[NN * DD];   // mean-aggregation buffer
__device__ __align__(16) float g_h1 [NN * DD];   // layer-1 output
__device__ int   g_deg[NN];        // in-degree
__device__ int   g_off[NN];        // CSR exclusive offsets
__device__ int   g_pos[NN];        // fill cursors
__device__ int   g_srt[NE];        // src ids grouped by dst
__device__ int   g_bsum[256];      // scan partials
__device__ int   g_mode;           // 1 = edge_index is int64, 0 = int32

typedef unsigned long long u64;

// packed 2x fp32 FMA (Blackwell FFMA2 — 2x throughput vs 3-reg FFMA)
__device__ __forceinline__ void ffma2(u64 &d, u64 a, u64 b) {
    asm("fma.rn.f32x2 %0, %1, %2, %0;" : "+l"(d) : "l"(a), "l"(b));
}

// fetch edge endpoint `idx` (element index in a (2,NE) array) per dtype mode
__device__ __forceinline__ int edge_at(const int* ei32, int mode, long long idx) {
    if (mode) return (int)reinterpret_cast<const long long*>(ei32)[idx];
    return ei32[idx];
}

// ---------------- dtype detection -------------------------------------------
// int64 node ids in [0, 2^31) have zero high words at every odd int32 slot.
__global__ void k_detect(const int* __restrict__ ei32) {
    int is64 = 1;
    for (int t = 0; t < 32; ++t)
        if (ei32[2 * t + 1] != 0) { is64 = 0; break; }
    g_mode = is64;
}

// ---------------- CSR build --------------------------------------------------
__global__ void k_init() {
    int i = blockIdx.x * blockDim.x + threadIdx.x;
    if (i < NN) { g_deg[i] = 0; g_pos[i] = 0; }
}

__global__ void k_hist(const int* __restrict__ ei32) {
    int e = blockIdx.x * blockDim.x + threadIdx.x;
    if (e >= NE) return;
    int d = edge_at(ei32, g_mode, (long long)NE + e);
    if (d >= 0 && d < NN) atomicAdd(&g_deg[d], 1);
}

__global__ void k_scan_partial() {
    __shared__ int sh[256];
    int t = threadIdx.x;
    int i = blockIdx.x * 256 + t;
    int v = (i < NN) ? g_deg[i] : 0;
    sh[t] = v; __syncthreads();
    for (int o = 128; o > 0; o >>= 1) {
        if (t < o) sh[t] += sh[t + o];
        __syncthreads();
    }
    if (t == 0) g_bsum[blockIdx.x] = sh[0];
}

__global__ void k_scan_base() {
    __shared__ int sh[256];
    int t = threadIdx.x;
    int v = (t < SCAN_BLKS) ? g_bsum[t] : 0;
    sh[t] = v; __syncthreads();
    for (int o = 1; o < 256; o <<= 1) {
        int x = (t >= o) ? sh[t - o] : 0;
        __syncthreads();
        sh[t] += x;
        __syncthreads();
    }
    if (t < SCAN_BLKS) g_bsum[t] = sh[t] - v;   // exclusive
}

__global__ void k_scan_final() {
    __shared__ int sh[256];
    int t = threadIdx.x;
    int i = blockIdx.x * 256 + t;
    int v = (i < NN) ? g_deg[i] : 0;
    sh[t] = v; __syncthreads();
    for (int o = 1; o < 256; o <<= 1) {
        int x = (t >= o) ? sh[t - o] : 0;
        __syncthreads();
        sh[t] += x;
        __syncthreads();
    }
    if (i < NN) g_off[i] = g_bsum[blockIdx.x] + sh[t] - v;  // exclusive
}

__global__ void k_fill(const int* __restrict__ ei32) {
    int e = blockIdx.x * blockDim.x + threadIdx.x;
    if (e >= NE) return;
    int mode = g_mode;
    int s = edge_at(ei32, mode, e);
    int d = edge_at(ei32, mode, (long long)NE + e);
    if (s < 0 || s >= NN || d < 0 || d >= NN) return;
    int p = atomicAdd(&g_pos[d], 1);
    g_srt[g_off[d] + p] = s;
}

// ---------------- gather mean aggregation: one warp per node -----------------
// LAYER 0: read x param; LAYER 1: read g_h1.
template<int LAYER>
__global__ void __launch_bounds__(256, 4)
k_agg(const float* __restrict__ x) {
    int node = (blockIdx.x * 256 + threadIdx.x) >> 5;
    if (node >= NN) return;
    int lane = threadIdx.x & 31;
    const float* h = (LAYER == 0) ? x : (const float*)g_h1;

    int beg = g_off[node];
    int n   = g_deg[node];

    float4 acc = make_float4(0.f, 0.f, 0.f, 0.f);
    int k = 0;
    for (; k + 4 <= n; k += 4) {
        int s0 = g_srt[beg + k];
        int s1 = g_srt[beg + k + 1];
        int s2 = g_srt[beg + k + 2];
        int s3 = g_srt[beg + k + 3];
        float4 v0 = *reinterpret_cast<const float4*>(h + (size_t)s0 * DD + lane * 4);
        float4 v1 = *reinterpret_cast<const float4*>(h + (size_t)s1 * DD + lane * 4);
        float4 v2 = *reinterpret_cast<const float4*>(h + (size_t)s2 * DD + lane * 4);
        float4 v3 = *reinterpret_cast<const float4*>(h + (size_t)s3 * DD + lane * 4);
        acc.x += v0.x + v1.x + v2.x + v3.x;
        acc.y += v0.y + v1.y + v2.y + v3.y;
        acc.z += v0.z + v1.z + v2.z + v3.z;
        acc.w += v0.w + v1.w + v2.w + v3.w;
    }
    for (; k < n; ++k) {
        int s = g_srt[beg + k];
        float4 v = *reinterpret_cast<const float4*>(h + (size_t)s * DD + lane * 4);
        acc.x += v.x; acc.y += v.y; acc.z += v.z; acc.w += v.w;
    }
    float inv = 1.f / fmaxf((float)n, 1.f);
    acc.x *= inv; acc.y *= inv; acc.z *= inv; acc.w *= inv;
    *reinterpret_cast<float4*>(g_agg + (size_t)node * DD + lane * 4) = acc;
}

// ---------------- fused GEMM:  out = act( [mean | h] @ [Wl|Wr]^T + b ) ------
// Block: 128 rows x 128 cols (full D). K = 256. FFMA2 microkernel:
// thread (ty,tx): rows ty*8..+7, col-pairs {tx*2 + j*32}. W resident in smem
// (k-major), A tile double-buffered with duplicated pairs for LDS.64 broadcast.
// LAYER 1: hin = x param, writes g_h1 (ReLU). LAYER 2: hin = g_h1, writes out
// (ReLU + LayerNorm).
template<int LAYER>
__global__ void __launch_bounds__(NTHR, 1)
k_gemm(const float* __restrict__ xin,
       const float* __restrict__ Wl, const float* __restrict__ Wr,
       const float* __restrict__ bias,
       const float* __restrict__ lnw, const float* __restrict__ lnb,
       float* __restrict__ outp)
{
    constexpr bool DO_LN = (LAYER == 2);
    extern __shared__ float smem[];
    float* Ws = smem;                       // [KTOT][DD] k-major = 128 KB
    float* As = smem + KTOT * DD;           // [2][BK][2*BM] duplicated = 64 KB

    const float* hin = (LAYER == 1) ? xin : (const float*)g_h1;
    float*       out = (LAYER == 1) ? (float*)g_h1 : outp;

    const int tid = threadIdx.x;
    const int r0  = blockIdx.x * BM;
    const int ty  = tid >> 4;     // 0..15
    const int tx  = tid & 15;     // 0..15

    // --- stage-0 A tile loads (from g_agg, k in [0,32))
    float4 pre[4];
    #pragma unroll
    for (int it = 0; it < 4; ++it) {
        int idx = tid + it * NTHR;
        int row = idx >> 3;
        int q   = idx & 7;
        int r   = r0 + row;
        float4 v = make_float4(0.f, 0.f, 0.f, 0.f);
        if (r < NN)
            v = *reinterpret_cast<const float4*>(g_agg + (size_t)r * DD + q * 4);
        pre[it] = v;
    }

    // --- load W (transpose to k-major): Ws[k*128 + j], k<128 = Wl, k>=128 = Wr
    #pragma unroll 4
    for (int it = 0; it < 32; ++it) {
        int idx = tid + it * NTHR;       // 0..8191 float4s
        int j   = idx & 127;
        int kq  = idx >> 7;              // combined-K float4 index (0..63)
        const float4* src = (kq < 32)
            ? reinterpret_cast<const float4*>(Wl + j * DD) + kq
            : reinterpret_cast<const float4*>(Wr + j * DD) + (kq - 32);
        float4 w = *src;
        int kb = kq * 4;
        Ws[(kb + 0) * DD + j] = w.x;
        Ws[(kb + 1) * DD + j] = w.y;
        Ws[(kb + 2) * DD + j] = w.z;
        Ws[(kb + 3) * DD + j] = w.w;
    }

    // store stage 0 (duplicated pairs for 64-bit broadcast loads)
    #pragma unroll
    for (int it = 0; it < 4; ++it) {
        int idx = tid + it * NTHR;
        int row = idx >> 3;
        int q   = idx & 7;
        float vv[4] = {pre[it].x, pre[it].y, pre[it].z, pre[it].w};
        #pragma unroll
        for (int m = 0; m < 4; ++m)
            *reinterpret_cast<float2*>(As + (q * 4 + m) * (2 * BM) + 2 * row)
                = make_float2(vv[m], vv[m]);
    }
    __syncthreads();   // Ws + As[0] ready

    u64 acc[8][4];
    #pragma unroll
    for (int i = 0; i < 8; ++i)
        #pragma unroll
        for (int j = 0; j < 4; ++j) acc[i][j] = 0ULL;

    int cur = 0;
    #pragma unroll 1
    for (int s = 0; s < 8; ++s) {
        // prefetch next stage from global (agg for s<4, h for s>=4)
        if (s < 7) {
            int sn = s + 1;
            const float* base = (sn < 4) ? (const float*)g_agg : hin;
            int koff = (sn < 4) ? sn * BK : (sn - 4) * BK;
            #pragma unroll
            for (int it = 0; it < 4; ++it) {
                int idx = tid + it * NTHR;
                int row = idx >> 3;
                int q   = idx & 7;
                int r   = r0 + row;
                float4 v = make_float4(0.f, 0.f, 0.f, 0.f);
                if (r < NN)
                    v = *reinterpret_cast<const float4*>(base + (size_t)r * DD + koff + q * 4);
                pre[it] = v;
            }
        }

        // compute BK k-steps on buffer `cur`
        const float* A = As + cur * (BK * 2 * BM);
        #pragma unroll 8
        for (int kk = 0; kk < BK; ++kk) {
            u64 a2[8], b2[4];
            const u64* Arow = reinterpret_cast<const u64*>(A + kk * (2 * BM));
            #pragma unroll
            for (int i = 0; i < 8; ++i) a2[i] = Arow[ty * 8 + i];
            const u64* Wk = reinterpret_cast<const u64*>(Ws + (s * BK + kk) * DD);
            #pragma unroll
            for (int j = 0; j < 4; ++j) b2[j] = Wk[tx + j * 16];
            #pragma unroll
            for (int i = 0; i < 8; ++i)
                #pragma unroll
                for (int j = 0; j < 4; ++j) ffma2(acc[i][j], a2[i], b2[j]);
        }

        if (s < 7) {
            float* An = As + (cur ^ 1) * (BK * 2 * BM);
            __syncthreads();   // all warps done reading An (read 2 stages ago)
            #pragma unroll
            for (int it = 0; it < 4; ++it) {
                int idx = tid + it * NTHR;
                int row = idx >> 3;
                int q   = idx & 7;
                float vv[4] = {pre[it].x, pre[it].y, pre[it].z, pre[it].w};
                #pragma unroll
                for (int m = 0; m < 4; ++m)
                    *reinterpret_cast<float2*>(An + (q * 4 + m) * (2 * BM) + 2 * row)
                        = make_float2(vv[m], vv[m]);
            }
            __syncthreads();
        }
        cur ^= 1;
    }

    // ---------------- epilogue: bias + ReLU (+ LayerNorm) ------------------
    float2 bv[4], lw[4], lb[4];
    #pragma unroll
    for (int j = 0; j < 4; ++j) {
        int c = tx * 2 + j * 32;
        bv[j] = *reinterpret_cast<const float2*>(bias + c);
        if (DO_LN) {
            lw[j] = *reinterpret_cast<const float2*>(lnw + c);
            lb[j] = *reinterpret_cast<const float2*>(lnb + c);
        }
    }

    #pragma unroll
    for (int i = 0; i < 8; ++i) {
        int r = r0 + ty * 8 + i;
        float v[8];
        #pragma unroll
        for (int j = 0; j < 4; ++j) {
            float2 f = *reinterpret_cast<float2*>(&acc[i][j]);
            v[2 * j]     = fmaxf(f.x + bv[j].x, 0.f);
            v[2 * j + 1] = fmaxf(f.y + bv[j].y, 0.f);
        }
        if (DO_LN) {
            float s1 = 0.f, s2 = 0.f;
            #pragma unroll
            for (int t = 0; t < 8; ++t) { s1 += v[t]; s2 += v[t] * v[t]; }
            #pragma unroll
            for (int m = 8; m >= 1; m >>= 1) {
                s1 += __shfl_xor_sync(0xffffffffu, s1, m, 16);
                s2 += __shfl_xor_sync(0xffffffffu, s2, m, 16);
            }
            float mu  = s1 * (1.f / 128.f);
            float var = s2 * (1.f / 128.f) - mu * mu;
            float sc  = rsqrtf(var + 1e-5f);
            if (r < NN) {
                #pragma unroll
                for (int j = 0; j < 4; ++j) {
                    int c = tx * 2 + j * 32;
                    float2 o;
                    o.x = (v[2 * j]     - mu) * sc * lw[j].x + lb[j].x;
                    o.y = (v[2 * j + 1] - mu) * sc * lw[j].y + lb[j].y;
                    *reinterpret_cast<float2*>(out + (size_t)r * DD + c) = o;
                }
            }
        } else {
            if (r < NN) {
                #pragma unroll
                for (int j = 0; j < 4; ++j) {
                    int c = tx * 2 + j * 32;
                    *reinterpret_cast<float2*>(out + (size_t)r * DD + c)
                        = make_float2(v[2 * j], v[2 * j + 1]);
                }
            }
        }
    }
}

// ---------------- launcher ---------------------------------------------------
extern "C" void kernel_launch(void* const* d_in, const int* in_sizes, int n_in,
                              void* d_out, int out_size) {
    const float* x   = (const float*)d_in[0];
    const int*   ei  = (const int*)  d_in[1];   // int32 OR int64 (auto-detected)
    const float* W1l = (const float*)d_in[2];
    const float* b1l = (const float*)d_in[3];
    const float* W1r = (const float*)d_in[4];
    const float* W2l = (const float*)d_in[5];
    const float* b2l = (const float*)d_in[6];
    const float* W2r = (const float*)d_in[7];
    const float* lnw = (const float*)d_in[8];
    const float* lnb = (const float*)d_in[9];
    float* out = (float*)d_out;

    const int SMEM = (KTOT * DD + 2 * BK * 2 * BM) * (int)sizeof(float); // 196608 B
    cudaFuncSetAttribute((const void*)k_gemm<1>,
                         cudaFuncAttributeMaxDynamicSharedMemorySize, SMEM);
    cudaFuncSetAttribute((const void*)k_gemm<2>,
                         cudaFuncAttributeMaxDynamicSharedMemorySize, SMEM);

    const int nb = (NN + 255) / 256;             // 196
    const int eb = (NE + 255) / 256;             // 3125
    const int ab = (NN * 32 + 255) / 256;        // 6250 (one warp per node)
    const int gb = (NN + BM - 1) / BM;           // 391

    // ---- CSR build (once; shared by both layers) ----
    k_detect<<<1, 1>>>(ei);
    k_init<<<nb, 256>>>();
    k_hist<<<eb, 256>>>(ei);
    k_scan_partial<<<SCAN_BLKS, 256>>>();
    k_scan_base<<<1, 256>>>();
    k_scan_final<<<SCAN_BLKS, 256>>>();
    k_fill<<<eb, 256>>>(ei);

    // ---- layer 1 ----
    k_agg<0><<<ab, 256>>>(x);
    k_gemm<1><<<gb, NTHR, SMEM>>>(x, W1l, W1r, b1l, nullptr, nullptr, nullptr);
    // ---- layer 2 ----
    k_agg<1><<<ab, 256>>>(nullptr);
    k_gemm<2><<<gb, NTHR, SMEM>>>(nullptr, W2l, W2r, b2l, lnw, lnb, out);
}

// round 7
// speedup vs baseline: 1.1951x; 1.1951x over previous
#include <cuda_runtime.h>
#include <cstdint>
#include <cstddef>

#define NN   50000
#define NE   800000
#define DD   128
#define KTOT 256
#define BM   128
#define BK   32
#define NTHR 256
#define NTILES ((NN + BM - 1) / BM)     // 391
#define GGRID 148                       // persistent GEMM grid (1 CTA/SM)
#define LDA  (2 * BM + 2)               // padded A-tile stride (bank-conflict fix)
#define SCAN_BLKS 196                   // ceil(50000/256)

// ---------------- scratch (device globals; no allocation allowed) -----------
__device__ __align__(16) float g_agg[NN * DD];   // mean-aggregation buffer
__device__ __align__(16) float g_h1 [NN * DD];   // layer-1 output
__device__ int   g_deg[NN];        // in-degree
__device__ int   g_off[NN];        // CSR exclusive offsets
__device__ int   g_pos[NN];        // fill cursors (init'd to g_off by scan_final)
__device__ int   g_srt[NE];        // src ids grouped by dst
__device__ int   g_bsum[256];      // scan partials
__device__ int   g_mode;           // 1 = edge_index is int64, 0 = int32

typedef unsigned long long u64;

// packed 2x fp32 FMA (Blackwell FFMA2 — 2x throughput vs 3-reg FFMA)
__device__ __forceinline__ void ffma2(u64 &d, u64 a, u64 b) {
    asm("fma.rn.f32x2 %0, %1, %2, %0;" : "+l"(d) : "l"(a), "l"(b));
}

// fetch edge endpoint `idx` (element index in a (2,NE) array) per dtype mode
__device__ __forceinline__ int edge_at(const int* ei32, int mode, long long idx) {
    if (mode) return (int)reinterpret_cast<const long long*>(ei32)[idx];
    return ei32[idx];
}

// ---------------- init + dtype detection ------------------------------------
// int64 node ids in [0, 2^31) have zero high words at every odd int32 slot.
__global__ void k_init(const int* __restrict__ ei32) {
    int i = blockIdx.x * blockDim.x + threadIdx.x;
    if (i < NN) g_deg[i] = 0;
    if (blockIdx.x == 0 && threadIdx.x == 0) {
        int is64 = 1;
        for (int t = 0; t < 32; ++t)
            if (ei32[2 * t + 1] != 0) { is64 = 0; break; }
        g_mode = is64;
    }
}

// ---------------- CSR build --------------------------------------------------
__global__ void k_hist(const int* __restrict__ ei32) {
    int e = blockIdx.x * blockDim.x + threadIdx.x;
    if (e >= NE) return;
    int d = edge_at(ei32, g_mode, (long long)NE + e);
    if (d >= 0 && d < NN) atomicAdd(&g_deg[d], 1);
}

__global__ void k_scan_partial() {
    __shared__ int sh[256];
    int t = threadIdx.x;
    int i = blockIdx.x * 256 + t;
    int v = (i < NN) ? g_deg[i] : 0;
    sh[t] = v; __syncthreads();
    for (int o = 128; o > 0; o >>= 1) {
        if (t < o) sh[t] += sh[t + o];
        __syncthreads();
    }
    if (t == 0) g_bsum[blockIdx.x] = sh[0];
}

__global__ void k_scan_base() {
    __shared__ int sh[256];
    int t = threadIdx.x;
    int v = (t < SCAN_BLKS) ? g_bsum[t] : 0;
    sh[t] = v; __syncthreads();
    for (int o = 1; o < 256; o <<= 1) {
        int x = (t >= o) ? sh[t - o] : 0;
        __syncthreads();
        sh[t] += x;
        __syncthreads();
    }
    if (t < SCAN_BLKS) g_bsum[t] = sh[t] - v;   // exclusive
}

__global__ void k_scan_final() {
    __shared__ int sh[256];
    int t = threadIdx.x;
    int i = blockIdx.x * 256 + t;
    int v = (i < NN) ? g_deg[i] : 0;
    sh[t] = v; __syncthreads();
    for (int o = 1; o < 256; o <<= 1) {
        int x = (t >= o) ? sh[t - o] : 0;
        __syncthreads();
        sh[t] += x;
        __syncthreads();
    }
    if (i < NN) {
        int off = g_bsum[blockIdx.x] + sh[t] - v;  // exclusive
        g_off[i] = off;
        g_pos[i] = off;                            // fill cursor starts at offset
    }
}

__global__ void k_fill(const int* __restrict__ ei32) {
    int e = blockIdx.x * blockDim.x + threadIdx.x;
    if (e >= NE) return;
    int mode = g_mode;
    int s = edge_at(ei32, mode, e);
    int d = edge_at(ei32, mode, (long long)NE + e);
    if (s < 0 || s >= NN || d < 0 || d >= NN) return;
    int p = atomicAdd(&g_pos[d], 1);
    g_srt[p] = s;
}

// ---------------- gather mean aggregation: one warp per node -----------------
template<int LAYER>
__global__ void __launch_bounds__(256, 4)
k_agg(const float* __restrict__ x) {
    int node = (blockIdx.x * 256 + threadIdx.x) >> 5;
    if (node >= NN) return;
    int lane = threadIdx.x & 31;
    const float* h = (LAYER == 0) ? x : (const float*)g_h1;

    int beg = g_off[node];
    int n   = g_deg[node];

    float4 acc = make_float4(0.f, 0.f, 0.f, 0.f);
    int k = 0;
    for (; k + 4 <= n; k += 4) {
        int s0 = g_srt[beg + k];
        int s1 = g_srt[beg + k + 1];
        int s2 = g_srt[beg + k + 2];
        int s3 = g_srt[beg + k + 3];
        float4 v0 = __ldg(reinterpret_cast<const float4*>(h + (size_t)s0 * DD + lane * 4));
        float4 v1 = __ldg(reinterpret_cast<const float4*>(h + (size_t)s1 * DD + lane * 4));
        float4 v2 = __ldg(reinterpret_cast<const float4*>(h + (size_t)s2 * DD + lane * 4));
        float4 v3 = __ldg(reinterpret_cast<const float4*>(h + (size_t)s3 * DD + lane * 4));
        acc.x += v0.x + v1.x + v2.x + v3.x;
        acc.y += v0.y + v1.y + v2.y + v3.y;
        acc.z += v0.z + v1.z + v2.z + v3.z;
        acc.w += v0.w + v1.w + v2.w + v3.w;
    }
    for (; k < n; ++k) {
        int s = g_srt[beg + k];
        float4 v = __ldg(reinterpret_cast<const float4*>(h + (size_t)s * DD + lane * 4));
        acc.x += v.x; acc.y += v.y; acc.z += v.z; acc.w += v.w;
    }
    float inv = 1.f / fmaxf((float)n, 1.f);
    acc.x *= inv; acc.y *= inv; acc.z *= inv; acc.w *= inv;
    *reinterpret_cast<float4*>(g_agg + (size_t)node * DD + lane * 4) = acc;
}

// ---------------- persistent fused GEMM --------------------------------------
// out = act( [mean | h] @ [Wl|Wr]^T + b ).  Grid = 148 persistent CTAs; each
// loops tiles bid, bid+148, ...  W (k-major, 128 KB smem) loaded ONCE per CTA.
// A tile double-buffered with duplicated pairs (LDS.64 broadcast), stride LDA
// = 258 to kill STS bank conflicts.  Stage-7 slot prefetches the NEXT tile's
// stage-0 A so inter-tile latency hides under the epilogue.
template<int LAYER>
__global__ void __launch_bounds__(NTHR, 1)
k_gemm(const float* __restrict__ xin,
       const float* __restrict__ Wl, const float* __restrict__ Wr,
       const float* __restrict__ bias,
       const float* __restrict__ lnw, const float* __restrict__ lnb,
       float* __restrict__ outp)
{
    constexpr bool DO_LN = (LAYER == 2);
    extern __shared__ float smem[];
    float* Ws = smem;                       // [KTOT][DD] k-major = 128 KB
    float* As = smem + KTOT * DD;           // [2][BK][LDA] duplicated pairs

    const float* hin = (LAYER == 1) ? xin : (const float*)g_h1;
    float*       out = (LAYER == 1) ? (float*)g_h1 : outp;

    const int tid = threadIdx.x;
    const int ty  = tid >> 4;     // 0..15
    const int tx  = tid & 15;     // 0..15

    // --- load W once (transpose to k-major): Ws[k*128+j]; k<128=Wl, k>=128=Wr
    #pragma unroll 4
    for (int it = 0; it < 32; ++it) {
        int idx = tid + it * NTHR;       // 0..8191 float4s
        int j   = idx & 127;
        int kq  = idx >> 7;              // combined-K float4 index (0..63)
        const float4* src = (kq < 32)
            ? reinterpret_cast<const float4*>(Wl + j * DD) + kq
            : reinterpret_cast<const float4*>(Wr + j * DD) + (kq - 32);
        float4 w = *src;
        int kb = kq * 4;
        Ws[(kb + 0) * DD + j] = w.x;
        Ws[(kb + 1) * DD + j] = w.y;
        Ws[(kb + 2) * DD + j] = w.z;
        Ws[(kb + 3) * DD + j] = w.w;
    }

    // --- epilogue constants (loop-invariant)
    float2 bv[4], lw[4], lb[4];
    #pragma unroll
    for (int j = 0; j < 4; ++j) {
        int c = tx * 2 + j * 32;
        bv[j] = *reinterpret_cast<const float2*>(bias + c);
        if (DO_LN) {
            lw[j] = *reinterpret_cast<const float2*>(lnw + c);
            lb[j] = *reinterpret_cast<const float2*>(lnb + c);
        }
    }

    // --- stage-0 A of the FIRST tile
    float4 pre[4];
    {
        int r0 = blockIdx.x * BM;
        #pragma unroll
        for (int it = 0; it < 4; ++it) {
            int idx = tid + it * NTHR;
            int row = idx >> 3;
            int q   = idx & 7;
            int r   = r0 + row;
            float4 v = make_float4(0.f, 0.f, 0.f, 0.f);
            if (r < NN)
                v = *reinterpret_cast<const float4*>(g_agg + (size_t)r * DD + q * 4);
            pre[it] = v;
        }
    }

    for (int tile = blockIdx.x; tile < NTILES; tile += GGRID) {
        const int r0 = tile * BM;

        __syncthreads();   // As free of previous tile's reads (and W writes, tile 0)
        // store stage 0 (duplicated pairs for 64-bit broadcast loads)
        #pragma unroll
        for (int it = 0; it < 4; ++it) {
            int idx = tid + it * NTHR;
            int row = idx >> 3;
            int q   = idx & 7;
            float vv[4] = {pre[it].x, pre[it].y, pre[it].z, pre[it].w};
            #pragma unroll
            for (int m = 0; m < 4; ++m)
                *reinterpret_cast<float2*>(As + (q * 4 + m) * LDA + 2 * row)
                    = make_float2(vv[m], vv[m]);
        }
        __syncthreads();

        u64 acc[8][4];
        #pragma unroll
        for (int i = 0; i < 8; ++i)
            #pragma unroll
            for (int j = 0; j < 4; ++j) acc[i][j] = 0ULL;

        int cur = 0;
        #pragma unroll 1
        for (int s = 0; s < 8; ++s) {
            // prefetch: stages 1..7 of this tile, or stage 0 of the next tile
            if (s < 7) {
                int sn = s + 1;
                const float* base = (sn < 4) ? (const float*)g_agg : hin;
                int koff = (sn < 4) ? sn * BK : (sn - 4) * BK;
                #pragma unroll
                for (int it = 0; it < 4; ++it) {
                    int idx = tid + it * NTHR;
                    int row = idx >> 3;
                    int q   = idx & 7;
                    int r   = r0 + row;
                    float4 v = make_float4(0.f, 0.f, 0.f, 0.f);
                    if (r < NN)
                        v = *reinterpret_cast<const float4*>(base + (size_t)r * DD + koff + q * 4);
                    pre[it] = v;
                }
            } else if (tile + GGRID < NTILES) {
                int rn0 = (tile + GGRID) * BM;
                #pragma unroll
                for (int it = 0; it < 4; ++it) {
                    int idx = tid + it * NTHR;
                    int row = idx >> 3;
                    int q   = idx & 7;
                    int r   = rn0 + row;
                    float4 v = make_float4(0.f, 0.f, 0.f, 0.f);
                    if (r < NN)
                        v = *reinterpret_cast<const float4*>(g_agg + (size_t)r * DD + q * 4);
                    pre[it] = v;
                }
            }

            // compute BK k-steps on buffer `cur`
            const float* A = As + cur * (BK * LDA);
            #pragma unroll 8
            for (int kk = 0; kk < BK; ++kk) {
                u64 a2[8], b2[4];
                const u64* Arow = reinterpret_cast<const u64*>(A + kk * LDA);
                #pragma unroll
                for (int i = 0; i < 8; ++i) a2[i] = Arow[ty * 8 + i];
                const u64* Wk = reinterpret_cast<const u64*>(Ws + (s * BK + kk) * DD);
                #pragma unroll
                for (int j = 0; j < 4; ++j) b2[j] = Wk[tx + j * 16];
                #pragma unroll
                for (int i = 0; i < 8; ++i)
                    #pragma unroll
                    for (int j = 0; j < 4; ++j) ffma2(acc[i][j], a2[i], b2[j]);
            }

            if (s < 7) {
                float* An = As + (cur ^ 1) * (BK * LDA);
                __syncthreads();   // all warps done reading An
                #pragma unroll
                for (int it = 0; it < 4; ++it) {
                    int idx = tid + it * NTHR;
                    int row = idx >> 3;
                    int q   = idx & 7;
                    float vv[4] = {pre[it].x, pre[it].y, pre[it].z, pre[it].w};
                    #pragma unroll
                    for (int m = 0; m < 4; ++m)
                        *reinterpret_cast<float2*>(An + (q * 4 + m) * LDA + 2 * row)
                            = make_float2(vv[m], vv[m]);
                }
                __syncthreads();
                cur ^= 1;
            }
        }

        // ---------------- epilogue: bias + ReLU (+ LayerNorm) ----------------
        #pragma unroll
        for (int i = 0; i < 8; ++i) {
            int r = r0 + ty * 8 + i;
            float v[8];
            #pragma unroll
            for (int j = 0; j < 4; ++j) {
                float2 f = *reinterpret_cast<float2*>(&acc[i][j]);
                v[2 * j]     = fmaxf(f.x + bv[j].x, 0.f);
                v[2 * j + 1] = fmaxf(f.y + bv[j].y, 0.f);
            }
            if (DO_LN) {
                float s1 = 0.f, s2 = 0.f;
                #pragma unroll
                for (int t = 0; t < 8; ++t) { s1 += v[t]; s2 += v[t] * v[t]; }
                #pragma unroll
                for (int m = 8; m >= 1; m >>= 1) {
                    s1 += __shfl_xor_sync(0xffffffffu, s1, m, 16);
                    s2 += __shfl_xor_sync(0xffffffffu, s2, m, 16);
                }
                float mu  = s1 * (1.f / 128.f);
                float var = s2 * (1.f / 128.f) - mu * mu;
                float sc  = rsqrtf(var + 1e-5f);
                if (r < NN) {
                    #pragma unroll
                    for (int j = 0; j < 4; ++j) {
                        int c = tx * 2 + j * 32;
                        float2 o;
                        o.x = (v[2 * j]     - mu) * sc * lw[j].x + lb[j].x;
                        o.y = (v[2 * j + 1] - mu) * sc * lw[j].y + lb[j].y;
                        *reinterpret_cast<float2*>(out + (size_t)r * DD + c) = o;
                    }
                }
            } else {
                if (r < NN) {
                    #pragma unroll
                    for (int j = 0; j < 4; ++j) {
                        int c = tx * 2 + j * 32;
                        *reinterpret_cast<float2*>(out + (size_t)r * DD + c)
                            = make_float2(v[2 * j], v[2 * j + 1]);
                    }
                }
            }
        }
    }
}

// ---------------- launcher ---------------------------------------------------
extern "C" void kernel_launch(void* const* d_in, const int* in_sizes, int n_in,
                              void* d_out, int out_size) {
    const float* x   = (const float*)d_in[0];
    const int*   ei  = (const int*)  d_in[1];   // int32 OR int64 (auto-detected)
    const float* W1l = (const float*)d_in[2];
    const float* b1l = (const float*)d_in[3];
    const float* W1r = (const float*)d_in[4];
    const float* W2l = (const float*)d_in[5];
    const float* b2l = (const float*)d_in[6];
    const float* W2r = (const float*)d_in[7];
    const float* lnw = (const float*)d_in[8];
    const float* lnb = (const float*)d_in[9];
    float* out = (float*)d_out;

    const int SMEM = (KTOT * DD + 2 * BK * LDA) * (int)sizeof(float); // 197120 B
    cudaFuncSetAttribute((const void*)k_gemm<1>,
                         cudaFuncAttributeMaxDynamicSharedMemorySize, SMEM);
    cudaFuncSetAttribute((const void*)k_gemm<2>,
                         cudaFuncAttributeMaxDynamicSharedMemorySize, SMEM);

    const int nb = (NN + 255) / 256;             // 196
    const int eb = (NE + 255) / 256;             // 3125
    const int ab = (NN * 32 + 255) / 256;        // 6250 (one warp per node)

    // ---- CSR build (once; shared by both layers) ----
    k_init<<<nb, 256>>>(ei);
    k_hist<<<eb, 256>>>(ei);
    k_scan_partial<<<SCAN_BLKS, 256>>>();
    k_scan_base<<<1, 256>>>();
    k_scan_final<<<SCAN_BLKS, 256>>>();
    k_fill<<<eb, 256>>>(ei);

    // ---- layer 1 ----
    k_agg<0><<<ab, 256>>>(x);
    k_gemm<1><<<GGRID, NTHR, SMEM>>>(x, W1l, W1r, b1l, nullptr, nullptr, nullptr);
    // ---- layer 2 ----
    k_agg<1><<<ab, 256>>>(nullptr);
    k_gemm<2><<<GGRID, NTHR, SMEM>>>(nullptr, W2l, W2r, b2l, lnw, lnb, out);
}